// round 8
// baseline (speedup 1.0000x reference)
#include <cuda_runtime.h>
#include <cuda_bf16.h>
#include <math.h>
#include <stdint.h>

// ---------------------------------------------------------------------------
// Mamba2 block, B=2, T=1024.
// R7: tcgen05 GEMMs (N=64 MMAs, single-buffer serialized pipeline, all-thread
// proxy fence) + probe/fixup safety net: sampled entries verified by fp32 dot;
// on mismatch the proven tf32 mma.sync GEMM recomputes everything.
// ---------------------------------------------------------------------------

#define B_     2
#define T_     1024
#define DM     2048
#define DIN    4096
#define DCONV  4224
#define DPROJ  8384
#define NH     64
#define NTOK   (B_ * T_)   // 2048

__device__ float g_u  [(size_t)NTOK * DM];
__device__ float g_zx [(size_t)NTOK * DPROJ];
__device__ float g_xbc[(size_t)NTOK * DCONV];
__device__ float g_dt [(size_t)NTOK * NH];
__device__ float g_dA [(size_t)NTOK * NH];
__device__ float g_y  [(size_t)NTOK * DIN];
__device__ int   g_flag1, g_flag2;

// bf16 split operands for tcgen05 path
__device__ __nv_bfloat16 g_uh [(size_t)NTOK * DM];
__device__ __nv_bfloat16 g_ul [(size_t)NTOK * DM];
__device__ __nv_bfloat16 g_w1h[(size_t)DPROJ * DM];
__device__ __nv_bfloat16 g_w1l[(size_t)DPROJ * DM];
__device__ __nv_bfloat16 g_yh [(size_t)NTOK * DIN];
__device__ __nv_bfloat16 g_yl [(size_t)NTOK * DIN];
__device__ __nv_bfloat16 g_w2h[(size_t)DM * DIN];
__device__ __nv_bfloat16 g_w2l[(size_t)DM * DIN];

__device__ __forceinline__ float sigmoidf_(float v) { return 1.f / (1.f + expf(-v)); }

__device__ __forceinline__ void split_bf(float x, __nv_bfloat16& h, __nv_bfloat16& l) {
    h = __float2bfloat16(x);
    l = __float2bfloat16(x - __bfloat162float(h));
}

__device__ __forceinline__ uint32_t smem_u32(const void* p) {
    return (uint32_t)__cvta_generic_to_shared(p);
}
#define CPA16(dst, src) asm volatile("cp.async.cg.shared.global [%0], [%1], 16;" :: "r"(dst), "l"(src))
#define CPA_COMMIT()    asm volatile("cp.async.commit_group;")

// Arch-specific feature gate: tcgen05.ld/wait/dealloc are a-only.
#if defined(__CUDA_ARCH__) && (defined(__CUDA_ARCH_FEAT_SM103_ALL) || defined(__CUDA_ARCH_FEAT_SM100_ALL))
#define TC5_PATH 1
#else
#define TC5_PATH 0
#endif

#define GSM_TC5 66560   // 1024 + 4*16384

#if TC5_PATH
__device__ __forceinline__ uint32_t elect_one_pred() {
    uint32_t pred;
    asm volatile("{\n\t.reg .pred p;\n\telect.sync _|p, 0xFFFFFFFF;\n\t"
                 "selp.b32 %0, 1, 0, p;\n\t}" : "=r"(pred));
    return pred;
}
#define TCGEN05_ALLOC(sa, n) \
    asm volatile("tcgen05.alloc.cta_group::1.sync.aligned.shared::cta.b32 [%0], %1;" \
                 :: "r"((uint32_t)(sa)), "r"((uint32_t)(n)) : "memory")
#define TCGEN05_DEALLOC(t, n) \
    asm volatile("tcgen05.dealloc.cta_group::1.sync.aligned.b32 %0, %1;" :: "r"(t), "r"((uint32_t)(n)))
#define TCGEN05_COMMIT(mb) \
    asm volatile("tcgen05.commit.cta_group::1.mbarrier::arrive::one.shared::cluster.b64 [%0];" \
                 :: "r"((uint32_t)(mb)) : "memory")
#define TCGEN05_FENCE_AFTER() asm volatile("tcgen05.fence::after_thread_sync;" ::: "memory")
#define TCGEN05_WAIT_LD()     asm volatile("tcgen05.wait::ld.sync.aligned;" ::: "memory")
#define FENCE_PROXY_ASYNC()   asm volatile("fence.proxy.async.shared::cta;" ::: "memory")

#define MBAR_INIT(mb, n) \
    asm volatile("mbarrier.init.shared.b64 [%0], %1;" :: "r"((uint32_t)(mb)), "r"((uint32_t)(n)) : "memory")
#define MBAR_INVAL(mb) \
    asm volatile("mbarrier.inval.shared.b64 [%0];" :: "r"((uint32_t)(mb)) : "memory")
#define MBAR_WAIT(mb, ph) do { \
    uint32_t _m = (uint32_t)(mb); uint32_t _p = (uint32_t)(ph); uint32_t _d; \
    asm volatile("{\n\t.reg .pred p;\n\t" \
        "mbarrier.try_wait.parity.acquire.cta.shared::cta.b64 p, [%1], %2;\n\t" \
        "selp.b32 %0, 1, 0, p;\n\t}" : "=r"(_d) : "r"(_m), "r"(_p) : "memory"); \
    if (!_d) { \
        asm volatile("{\n\t.reg .pred P1;\n\tWL_%=:\n\t" \
            "mbarrier.try_wait.parity.acquire.cta.shared::cta.b64 P1, [%0], %1, 0x989680;\n\t" \
            "@P1 bra.uni WD_%=;\n\tbra.uni WL_%=;\n\tWD_%=:\n\t}" \
            :: "r"(_m), "r"(_p) : "memory"); \
    } } while (0)

#define TCLD32(r, ta) \
    asm volatile("tcgen05.ld.sync.aligned.32x32b.x32.b32 " \
        "{%0,%1,%2,%3,%4,%5,%6,%7,%8,%9,%10,%11,%12,%13,%14,%15," \
        "%16,%17,%18,%19,%20,%21,%22,%23,%24,%25,%26,%27,%28,%29,%30,%31}, [%32];" \
        : "=r"((r)[0]),"=r"((r)[1]),"=r"((r)[2]),"=r"((r)[3]),"=r"((r)[4]),"=r"((r)[5]), \
          "=r"((r)[6]),"=r"((r)[7]),"=r"((r)[8]),"=r"((r)[9]),"=r"((r)[10]),"=r"((r)[11]), \
          "=r"((r)[12]),"=r"((r)[13]),"=r"((r)[14]),"=r"((r)[15]),"=r"((r)[16]),"=r"((r)[17]), \
          "=r"((r)[18]),"=r"((r)[19]),"=r"((r)[20]),"=r"((r)[21]),"=r"((r)[22]),"=r"((r)[23]), \
          "=r"((r)[24]),"=r"((r)[25]),"=r"((r)[26]),"=r"((r)[27]),"=r"((r)[28]),"=r"((r)[29]), \
          "=r"((r)[30]),"=r"((r)[31]) : "r"(ta))

// SW128 K-major smem descriptor (Blackwell): layout=2, ver=1, SBO=64, LBO=1
static constexpr uint64_t SMEM_DESC_BASE_SW128 =
    (uint64_t(2) << 61) | (uint64_t(1) << 46) | (uint64_t(64) << 32) | (uint64_t(1) << 16);
#define MK_DESC(ba) (SMEM_DESC_BASE_SW128 | ((uint64_t)((ba) >> 4) & 0x3FFF))

__device__ __forceinline__ void mma_f16_ss(uint32_t d, uint64_t a, uint64_t b,
                                           uint32_t idesc, bool accum) {
    uint32_t en = accum ? 1u : 0u, z = 0u;
    asm volatile("{\n\t.reg .pred p;\n\tsetp.ne.u32 p, %5, 0;\n\t"
        "tcgen05.mma.cta_group::1.kind::f16 [%0], %1, %2, %3, {%4,%4,%4,%4}, p;\n\t}"
        :: "r"(d), "l"(a), "l"(b), "r"(idesc), "r"(z), "r"(en) : "memory");
}
// idesc: F32 accum, BF16 a/b, M=128, N=64 (all fields example-validated)
static constexpr uint32_t IDESC64 =
    (1u << 4) | (1u << 7) | (1u << 10) | ((64u / 8u) << 17) | ((128u / 16u) << 24);
#endif  // TC5_PATH

// tf32 helpers (fixup path — both passes)
__device__ __forceinline__ uint32_t f2tf(float x) {
    uint32_t r;
    asm("cvt.rna.tf32.f32 %0, %1;" : "=r"(r) : "f"(x));
    return r;
}
#define MMA8(d, a, b0v, b1v) asm volatile( \
    "mma.sync.aligned.m16n8k8.row.col.f32.tf32.tf32.f32 " \
    "{%0,%1,%2,%3},{%4,%5,%6,%7},{%8,%9},{%0,%1,%2,%3};" \
    : "+f"(d[0]), "+f"(d[1]), "+f"(d[2]), "+f"(d[3]) \
    : "r"(a[0]), "r"(a[1]), "r"(a[2]), "r"(a[3]), "r"(b0v), "r"(b1v))

// ---------------------------------------------------------------------------
// LayerNorm + bf16 split of u
// ---------------------------------------------------------------------------
__global__ void ln_kernel(const float* __restrict__ x,
                          const float* __restrict__ w,
                          const float* __restrict__ bb) {
    int r = blockIdx.x;
    const float* xr = x + (size_t)r * DM;
    float s = 0.f, s2 = 0.f;
    for (int i = threadIdx.x; i < DM; i += blockDim.x) {
        float v = xr[i]; s += v; s2 += v * v;
    }
    __shared__ float shs[32], shs2[32];
    int lane = threadIdx.x & 31, wid = threadIdx.x >> 5;
#pragma unroll
    for (int o = 16; o; o >>= 1) {
        s  += __shfl_xor_sync(0xffffffffu, s, o);
        s2 += __shfl_xor_sync(0xffffffffu, s2, o);
    }
    if (lane == 0) { shs[wid] = s; shs2[wid] = s2; }
    __syncthreads();
    __shared__ float mu_s, inv_s;
    if (threadIdx.x == 0) {
        float ts = 0.f, ts2 = 0.f;
        int nw = blockDim.x >> 5;
        for (int i = 0; i < nw; i++) { ts += shs[i]; ts2 += shs2[i]; }
        float mu = ts / DM;
        mu_s = mu;
        inv_s = rsqrtf(ts2 / DM - mu * mu + 1e-5f);
    }
    __syncthreads();
    float mu = mu_s, inv = inv_s;
    for (int i = threadIdx.x; i < DM; i += blockDim.x) {
        float v = (xr[i] - mu) * inv * w[i] + bb[i];
        size_t idx = (size_t)r * DM + i;
        g_u[idx] = v;
        __nv_bfloat16 h, l; split_bf(v, h, l);
        g_uh[idx] = h; g_ul[idx] = l;
    }
}

// ---------------------------------------------------------------------------
// Weight split: fp32 -> bf16 hi/lo
// ---------------------------------------------------------------------------
__global__ void wsplit_kernel(const float* __restrict__ W,
                              __nv_bfloat16* __restrict__ H,
                              __nv_bfloat16* __restrict__ L, int n4) {
    int i = blockIdx.x * blockDim.x + threadIdx.x;
    if (i >= n4) return;
    float4 v = reinterpret_cast<const float4*>(W)[i];
    __nv_bfloat16 h0, l0, h1, l1, h2, l2, h3, l3;
    split_bf(v.x, h0, l0); split_bf(v.y, h1, l1);
    split_bf(v.z, h2, l2); split_bf(v.w, h3, l3);
    reinterpret_cast<__nv_bfloat162*>(H)[i * 2 + 0] = __nv_bfloat162(h0, h1);
    reinterpret_cast<__nv_bfloat162*>(H)[i * 2 + 1] = __nv_bfloat162(h2, h3);
    reinterpret_cast<__nv_bfloat162*>(L)[i * 2 + 0] = __nv_bfloat162(l0, l1);
    reinterpret_cast<__nv_bfloat162*>(L)[i * 2 + 1] = __nv_bfloat162(l2, l3);
}

// ---------------------------------------------------------------------------
// tcgen05 GEMM NT (3-term bf16 split). 128x128 CTA tile, K-chunk 64,
// single-buffered, serialized per chunk. N=64 MMAs into two D-halves.
// Empty body when TC5_PATH==0 (probe/fixup then takes over).
// ---------------------------------------------------------------------------
template<bool GUARD_N, bool RES>
__device__ void gemm_tc5_body(const __nv_bfloat16* __restrict__ Ah,
                              const __nv_bfloat16* __restrict__ Al,
                              const __nv_bfloat16* __restrict__ Bh,
                              const __nv_bfloat16* __restrict__ Bl,
                              const float* __restrict__ Res,
                              float* __restrict__ C, int N, int K) {
#if TC5_PATH
    extern __shared__ __align__(1024) char smem[];
    const uint32_t sb = smem_u32(smem);
    const int tid = threadIdx.x, wid = tid >> 5, lane = tid & 31;
    const int m0 = blockIdx.y * 128, n0 = blockIdx.x * 128;

    if (wid == 0) TCGEN05_ALLOC(sb, 128);
    if (tid == 0) MBAR_INIT(sb + 8, 1);
    __syncthreads();
    uint32_t tmem;
    asm volatile("ld.shared.b32 %0, [%1];" : "=r"(tmem) : "r"(sb));

    int phase = 0;
    const int NC = K >> 6;
    for (int c = 0; c < NC; c++) {
        const __nv_bfloat16* srcs[4] = { Ah, Al, Bh, Bl };
#pragma unroll
        for (int t = 0; t < 4; t++) {
            const __nv_bfloat16* S = srcs[t];
            const bool isB = (t >= 2);
#pragma unroll
            for (int i = 0; i < 4; i++) {
                int id = tid + 256 * i;       // 0..1023
                int row = id >> 3, c16 = id & 7;
                int grow = (isB ? n0 : m0) + row;
                if (GUARD_N && isB && grow >= N) grow = N - 1;
                const void* src = S + (size_t)grow * K + c * 64 + c16 * 8;
                uint32_t dst = sb + 1024u + (uint32_t)t * 16384u
                             + (uint32_t)(row * 128) + 16u * (uint32_t)(c16 ^ (row & 7));
                CPA16(dst, src);
            }
        }
        CPA_COMMIT();
        asm volatile("cp.async.wait_group 0;");
        __syncthreads();
        FENCE_PROXY_ASYNC();          // all threads: order cp.async data to async proxy
        __syncthreads();
        if (wid == 0 && elect_one_pred()) {
            uint64_t dAh = MK_DESC(sb + 1024);
            uint64_t dAl = MK_DESC(sb + 1024 + 16384);
            uint64_t dBh = MK_DESC(sb + 1024 + 32768);
            uint64_t dBl = MK_DESC(sb + 1024 + 49152);
#pragma unroll
            for (int ks = 0; ks < 4; ks++) {
#pragma unroll
                for (int h = 0; h < 2; h++) {
                    uint32_t d = tmem + h * 64;
                    uint64_t bh = dBh + h * 512 + ks * 2;   // +512 units = +8KB = 64 B-rows
                    uint64_t bl = dBl + h * 512 + ks * 2;
                    bool first = (c == 0 && ks == 0);
                    mma_f16_ss(d, dAh + ks * 2, bh, IDESC64, !first);
                    mma_f16_ss(d, dAl + ks * 2, bh, IDESC64, true);
                    mma_f16_ss(d, dAh + ks * 2, bl, IDESC64, true);
                }
            }
            TCGEN05_COMMIT(sb + 8);
        }
        MBAR_WAIT(sb + 8, phase);
        phase ^= 1;
    }
    TCGEN05_FENCE_AFTER();

    if (wid < 4) {
        int m = m0 + wid * 32 + lane;
#pragma unroll
        for (int q = 0; q < 4; q++) {
            uint32_t regs[32];
            TCLD32(regs, tmem + q * 32);
            TCGEN05_WAIT_LD();
            int nb = n0 + q * 32;
            for (int j = 0; j < 32; j++) {
                int n = nb + j;
                if (GUARD_N && n >= N) break;
                float v = __uint_as_float(regs[j]);
                if (RES) v += Res[(size_t)m * N + n];
                C[(size_t)m * N + n] = v;
            }
        }
    }
    __syncthreads();
    if (tid == 0) MBAR_INVAL(sb + 8);
    __syncthreads();
    if (wid == 0) TCGEN05_DEALLOC(tmem, 128);
#endif
}

__global__ __launch_bounds__(256)
void gemm1_tc5() {
    gemm_tc5_body<true, false>(g_uh, g_ul, g_w1h, g_w1l, nullptr, g_zx, DPROJ, DM);
}
__global__ __launch_bounds__(256)
void gemm2_tc5(const float* __restrict__ Res, float* __restrict__ out) {
    gemm_tc5_body<false, true>(g_yh, g_yl, g_w2h, g_w2l, Res, out, DM, DIN);
}

// ---------------------------------------------------------------------------
// Probe + fixup machinery.
// ---------------------------------------------------------------------------
#define NPROBE 64
__global__ void preclear1_kernel() {
    int s = threadIdx.x;
    if (s == 0) g_flag1 = 0;
    if (s < NPROBE) {
        int m = (s * 997) % NTOK, n = (s * 5003) % DPROJ;
        g_zx[(size_t)m * DPROJ + n] = 0.f;
    }
}
__global__ void probe1_kernel(const float* __restrict__ W) {
    __shared__ float sred[256];
    int s = blockIdx.x;
    int m = (s * 997) % NTOK, n = (s * 5003) % DPROJ;
    const float* ur = g_u + (size_t)m * DM;
    const float* wr = W + (size_t)n * DM;
    float acc = 0.f;
    for (int k = threadIdx.x; k < DM; k += 256) acc += ur[k] * wr[k];
    sred[threadIdx.x] = acc; __syncthreads();
    for (int o = 128; o; o >>= 1) {
        if (threadIdx.x < o) sred[threadIdx.x] += sred[threadIdx.x + o];
        __syncthreads();
    }
    if (threadIdx.x == 0) {
        float got = g_zx[(size_t)m * DPROJ + n];
        if (fabsf(got - sred[0]) > 0.03f) atomicExch(&g_flag1, 1);
    }
}
__global__ void preclear2_kernel(float* __restrict__ out) {
    int s = threadIdx.x;
    if (s == 0) g_flag2 = 0;
    if (s < NPROBE) {
        int m = (s * 997) % NTOK, n = (s * 131) % DM;
        out[(size_t)m * DM + n] = 0.f;
    }
}
__global__ void probe2_kernel(const float* __restrict__ W2,
                              const float* __restrict__ x,
                              const float* __restrict__ out) {
    __shared__ float sred[256];
    int s = blockIdx.x;
    int m = (s * 997) % NTOK, n = (s * 131) % DM;
    const float* yr = g_y + (size_t)m * DIN;
    const float* wr = W2 + (size_t)n * DIN;
    float acc = 0.f;
    for (int k = threadIdx.x; k < DIN; k += 256) acc += yr[k] * wr[k];
    sred[threadIdx.x] = acc; __syncthreads();
    for (int o = 128; o; o >>= 1) {
        if (threadIdx.x < o) sred[threadIdx.x] += sred[threadIdx.x + o];
        __syncthreads();
    }
    if (threadIdx.x == 0) {
        float truth = sred[0] + x[(size_t)m * DM + n];
        if (fabsf(out[(size_t)m * DM + n] - truth) > 0.03f) atomicExch(&g_flag2, 1);
    }
}

// tf32 fixup GEMM (R4-proven, static 40KB smem), early-exit on flag==0
#define GPITCH 20
#define GASZ   (128 * GPITCH)
template<bool GUARD_N, bool RES>
__device__ void gemm_tf32_body(const float* __restrict__ A,
                               const float* __restrict__ Bw,
                               const float* __restrict__ Res,
                               float* __restrict__ C, int N, int K) {
    __shared__ __align__(16) float smf[4 * GASZ];
    float* AsS[2] = { smf,        smf + 2 * GASZ };
    float* BsS[2] = { smf + GASZ, smf + 3 * GASZ };

    const int tid  = threadIdx.x;
    const int lane = tid & 31;
    const int wid  = tid >> 5;
    const int g    = lane >> 2;
    const int tg   = lane & 3;
    const int wm0  = (wid & 3) * 32;
    const int wn0  = (wid >> 2) * 64;
    const int m0   = blockIdx.y * 128;
    const int n0   = blockIdx.x * 128;

    float acc[2][8][4];
#pragma unroll
    for (int i = 0; i < 2; i++)
#pragma unroll
        for (int j = 0; j < 8; j++)
#pragma unroll
            for (int q = 0; q < 4; q++) acc[i][j][q] = 0.f;

    auto load_tile = [&](int st, int k0) {
#pragma unroll
        for (int i = 0; i < 2; i++) {
            int c = tid + 256 * i;
            int row = c >> 2, col4 = (c & 3) * 4;
            CPA16(smem_u32(&AsS[st][row * GPITCH + col4]),
                  A + (size_t)(m0 + row) * K + k0 + col4);
        }
#pragma unroll
        for (int i = 0; i < 2; i++) {
            int c = tid + 256 * i;
            int row = c >> 2, col4 = (c & 3) * 4;
            int br = n0 + row;
            if (GUARD_N && br >= N) br = N - 1;
            CPA16(smem_u32(&BsS[st][row * GPITCH + col4]),
                  Bw + (size_t)br * K + k0 + col4);
        }
        CPA_COMMIT();
    };

    const int KT = K >> 4;
    load_tile(0, 0);

    for (int kt = 0; kt < KT; kt++) {
        int cur = kt & 1;
        asm volatile("cp.async.wait_group 0;");
        __syncthreads();
        if (kt + 1 < KT) load_tile(cur ^ 1, (kt + 1) << 4);

        const float* Ac = AsS[cur];
        const float* Bc = BsS[cur];
#pragma unroll
        for (int k8 = 0; k8 < 2; k8++) {
            int kb = k8 * 8;
            uint32_t af[2][4];
#pragma unroll
            for (int i = 0; i < 2; i++) {
                const float* ap = &Ac[(wm0 + i * 16 + g) * GPITCH + kb + tg];
                af[i][0] = f2tf(ap[0]);
                af[i][1] = f2tf(ap[8 * GPITCH]);
                af[i][2] = f2tf(ap[4]);
                af[i][3] = f2tf(ap[8 * GPITCH + 4]);
            }
#pragma unroll
            for (int j = 0; j < 8; j++) {
                const float* bp = &Bc[(wn0 + j * 8 + g) * GPITCH + kb + tg];
                uint32_t b0 = f2tf(bp[0]);
                uint32_t b1 = f2tf(bp[4]);
                MMA8(acc[0][j], af[0], b0, b1);
                MMA8(acc[1][j], af[1], b0, b1);
            }
        }
    }
    __syncthreads();

#pragma unroll
    for (int i = 0; i < 2; i++) {
        int m = m0 + wm0 + i * 16 + g;
#pragma unroll
        for (int j = 0; j < 8; j++) {
            int n = n0 + wn0 + j * 8 + 2 * tg;
            if (GUARD_N && n >= N) continue;
            float2 v0 = make_float2(acc[i][j][0], acc[i][j][1]);
            float2 v1 = make_float2(acc[i][j][2], acc[i][j][3]);
            if (RES) {
                float2 r0 = *(const float2*)&Res[(size_t)m * N + n];
                float2 r1 = *(const float2*)&Res[(size_t)(m + 8) * N + n];
                v0.x += r0.x; v0.y += r0.y;
                v1.x += r1.x; v1.y += r1.y;
            }
            *(float2*)&C[(size_t)m * N + n]       = v0;
            *(float2*)&C[(size_t)(m + 8) * N + n] = v1;
        }
    }
}

__global__ __launch_bounds__(256, 2)
void gemm1_fix(const float* __restrict__ W) {
    if (g_flag1 == 0) return;
    gemm_tf32_body<true, false>(g_u, W, nullptr, g_zx, DPROJ, DM);
}
__global__ __launch_bounds__(256, 2)
void gemm2_fix(const float* __restrict__ W, const float* __restrict__ Res,
               float* __restrict__ out) {
    if (g_flag2 == 0) return;
    gemm_tf32_body<false, true>(g_y, W, Res, out, DM, DIN);
}

// ---------------------------------------------------------------------------
// Exact fp32 dt: dtraw[t,h] = u[t,:] . W[8320+h,:], then softplus + dA.
// ---------------------------------------------------------------------------
#define DTTOK 4
__global__ __launch_bounds__(256)
void dtexact_kernel(const float* __restrict__ W,
                    const float* __restrict__ dt_bias,
                    const float* __restrict__ A_log) {
    __shared__ float su[DTTOK][DM];
    int t0 = blockIdx.x * DTTOK;
    int tid = threadIdx.x, lane = tid & 31, wid = tid >> 5;
    for (int i = tid; i < DTTOK * DM; i += 256) {
        int tt = i >> 11, k = i & (DM - 1);
        su[tt][k] = g_u[(size_t)(t0 + tt) * DM + k];
    }
    __syncthreads();
    const float* Wdt = W + (size_t)(DPROJ - NH) * DM;
    for (int hb = 0; hb < 8; hb++) {
        int h = hb * 8 + wid;
        const float* wr = Wdt + (size_t)h * DM;
        float wreg[64];
#pragma unroll
        for (int i = 0; i < 64; i++) wreg[i] = wr[lane + 32 * i];
#pragma unroll
        for (int tt = 0; tt < DTTOK; tt++) {
            float acc = 0.f;
#pragma unroll
            for (int i = 0; i < 64; i++)
                acc = fmaf(wreg[i], su[tt][lane + 32 * i], acc);
#pragma unroll
            for (int o = 16; o; o >>= 1)
                acc += __shfl_xor_sync(0xffffffffu, acc, o);
            if (lane == 0) {
                float raw = acc + dt_bias[h];
                float dtv = (raw > 20.f) ? raw : log1pf(expf(raw));
                float Av = -expf(A_log[h]);
                int r = t0 + tt;
                g_dt[r * NH + h] = dtv;
                g_dA[r * NH + h] = expf(dtv * Av);
            }
        }
    }
}

// ---------------------------------------------------------------------------
// Depthwise causal conv (k=4) + SiLU.
// ---------------------------------------------------------------------------
#define CCH 32
__global__ void conv_kernel(const float* __restrict__ cw,
                            const float* __restrict__ cb) {
    int c = blockIdx.x * blockDim.x + threadIdx.x;
    if (c >= DCONV) return;
    int b = blockIdx.y >> 5;
    int chunk = blockIdx.y & 31;
    int t0 = chunk * CCH;
    float w0 = cw[c * 4 + 0], w1 = cw[c * 4 + 1];
    float w2 = cw[c * 4 + 2], w3 = cw[c * 4 + 3];
    float bias = cb[c];
    const float* src = g_zx + (size_t)b * T_ * DPROJ + DIN + c;
    float* dst = g_xbc + (size_t)b * T_ * DCONV + c;
    float x0 = (t0 >= 3) ? src[(size_t)(t0 - 3) * DPROJ] : 0.f;
    float x1 = (t0 >= 2) ? src[(size_t)(t0 - 2) * DPROJ] : 0.f;
    float x2 = (t0 >= 1) ? src[(size_t)(t0 - 1) * DPROJ] : 0.f;
    for (int t = t0; t < t0 + CCH; t++) {
        float x3 = src[(size_t)t * DPROJ];
        float v = bias + x0 * w0 + x1 * w1 + x2 * w2 + x3 * w3;
        v = v * sigmoidf_(v);
        dst[(size_t)t * DCONV] = v;
        x0 = x1; x1 = x2; x2 = x3;
    }
}

// ---------------------------------------------------------------------------
// Sequential selective scan. Block = (b, head), 64 threads (thread = p).
// ---------------------------------------------------------------------------
__global__ __launch_bounds__(64)
void scan_kernel(const float* __restrict__ Dvec) {
    int bh = blockIdx.x;
    int b = bh >> 6, hh = bh & 63;
    int p = threadIdx.x;

    __shared__ __align__(16) float sB[2][64];
    __shared__ __align__(16) float sC[2][64];
    __shared__ __align__(16) float sX[2][64];
    __shared__ float sS[2][2];

    float st[64];
#pragma unroll
    for (int n = 0; n < 64; n++) st[n] = 0.f;
    float Dh = Dvec[hh];

    const size_t base = (size_t)b * T_ * DCONV;
    {
        sX[0][p] = g_xbc[base + hh * 64 + p];
        sB[0][p] = g_xbc[base + 4096 + p];
        sC[0][p] = g_xbc[base + 4160 + p];
        if (p < 2) {
            int rr = b * T_;
            sS[0][p] = (p == 0) ? g_dA[rr * NH + hh] : g_dt[rr * NH + hh];
        }
    }

    for (int t = 0; t < T_; t++) {
        int buf = t & 1;
        __syncthreads();
        if (t + 1 < T_) {
            size_t rq = base + (size_t)(t + 1) * DCONV;
            sX[buf ^ 1][p] = g_xbc[rq + hh * 64 + p];
            sB[buf ^ 1][p] = g_xbc[rq + 4096 + p];
            sC[buf ^ 1][p] = g_xbc[rq + 4160 + p];
            if (p < 2) {
                int rr = b * T_ + t + 1;
                sS[buf ^ 1][p] = (p == 0) ? g_dA[rr * NH + hh] : g_dt[rr * NH + hh];
            }
        }
        float dAv = sS[buf][0];
        float dtx = sS[buf][1] * sX[buf][p];
        float acc = 0.f;
#pragma unroll
        for (int q = 0; q < 16; q++) {
            float4 b4 = *reinterpret_cast<const float4*>(&sB[buf][q * 4]);
            float4 c4 = *reinterpret_cast<const float4*>(&sC[buf][q * 4]);
            st[q * 4 + 0] = st[q * 4 + 0] * dAv + dtx * b4.x;
            st[q * 4 + 1] = st[q * 4 + 1] * dAv + dtx * b4.y;
            st[q * 4 + 2] = st[q * 4 + 2] * dAv + dtx * b4.z;
            st[q * 4 + 3] = st[q * 4 + 3] * dAv + dtx * b4.w;
            acc = fmaf(st[q * 4 + 0], c4.x, acc);
            acc = fmaf(st[q * 4 + 1], c4.y, acc);
            acc = fmaf(st[q * 4 + 2], c4.z, acc);
            acc = fmaf(st[q * 4 + 3], c4.w, acc);
        }
        g_y[(size_t)(b * T_ + t) * DIN + hh * 64 + p] = acc + Dh * sX[buf][p];
    }
}

// ---------------------------------------------------------------------------
// y = y * silu(z); RMSNorm * norm_w; emit fp32 + bf16 hi/lo. Block per token.
// ---------------------------------------------------------------------------
__global__ void gate_rms_kernel(const float* __restrict__ norm_w) {
    int r = blockIdx.x;
    float ss = 0.f;
    for (int i = threadIdx.x; i < DIN; i += blockDim.x) {
        float zv = g_zx[(size_t)r * DPROJ + i];
        float g = g_y[(size_t)r * DIN + i] * zv * sigmoidf_(zv);
        g_y[(size_t)r * DIN + i] = g;
        ss += g * g;
    }
    __shared__ float sh[32];
    int lane = threadIdx.x & 31, wid = threadIdx.x >> 5;
#pragma unroll
    for (int o = 16; o; o >>= 1) ss += __shfl_xor_sync(0xffffffffu, ss, o);
    if (lane == 0) sh[wid] = ss;
    __syncthreads();
    __shared__ float sc;
    if (threadIdx.x == 0) {
        float tot = 0.f;
        int nw = blockDim.x >> 5;
        for (int i = 0; i < nw; i++) tot += sh[i];
        sc = rsqrtf(tot / DIN + 1e-5f);
    }
    __syncthreads();
    float s = sc;
    for (int i = threadIdx.x; i < DIN; i += blockDim.x) {
        size_t idx = (size_t)r * DIN + i;
        float v = g_y[idx] * s * norm_w[i];
        g_y[idx] = v;
        __nv_bfloat16 h, l; split_bf(v, h, l);
        g_yh[idx] = h; g_yl[idx] = l;
    }
}

// ---------------------------------------------------------------------------
// launch
// ---------------------------------------------------------------------------
extern "C" void kernel_launch(void* const* d_in, const int* in_sizes, int n_in,
                              void* d_out, int out_size) {
    const float* x          = (const float*)d_in[0];
    const float* ln_w       = (const float*)d_in[1];
    const float* ln_b       = (const float*)d_in[2];
    const float* in_proj_w  = (const float*)d_in[3];
    const float* conv_w     = (const float*)d_in[4];
    const float* conv_b     = (const float*)d_in[5];
    const float* dt_bias    = (const float*)d_in[6];
    const float* A_log      = (const float*)d_in[7];
    const float* Dv         = (const float*)d_in[8];
    const float* norm_w     = (const float*)d_in[9];
    const float* out_proj_w = (const float*)d_in[10];
    float* out = (float*)d_out;

    cudaFuncSetAttribute(gemm1_tc5, cudaFuncAttributeMaxDynamicSharedMemorySize, GSM_TC5);
    cudaFuncSetAttribute(gemm2_tc5, cudaFuncAttributeMaxDynamicSharedMemorySize, GSM_TC5);

    {
        int n1 = DPROJ * DM / 4, n2 = DM * DIN / 4;
        wsplit_kernel<<<(n1 + 255) / 256, 256>>>(in_proj_w, g_w1h, g_w1l, n1);
        wsplit_kernel<<<(n2 + 255) / 256, 256>>>(out_proj_w, g_w2h, g_w2l, n2);
    }

    ln_kernel<<<NTOK, 256>>>(x, ln_w, ln_b);
    dtexact_kernel<<<NTOK / DTTOK, 256>>>(in_proj_w, dt_bias, A_log);

    preclear1_kernel<<<1, 64>>>();
    gemm1_tc5<<<dim3((DPROJ + 127) / 128, NTOK / 128), 256, GSM_TC5>>>();
    probe1_kernel<<<NPROBE, 256>>>(in_proj_w);
    gemm1_fix<<<dim3((DPROJ + 127) / 128, NTOK / 128), 256>>>(in_proj_w);

    conv_kernel<<<dim3((DCONV + 255) / 256, B_ * 32), 256>>>(conv_w, conv_b);
    scan_kernel<<<B_ * NH, 64>>>(Dv);
    gate_rms_kernel<<<NTOK, 256>>>(norm_w);

    preclear2_kernel<<<1, 64>>>(out);
    gemm2_tc5<<<dim3(DM / 128, NTOK / 128), 256, GSM_TC5>>>(x, out);
    probe2_kernel<<<NPROBE, 256>>>(out_proj_w, x, out);
    gemm2_fix<<<dim3(DM / 128, NTOK / 128), 256>>>(out_proj_w, x, out);
}

// round 12
// speedup vs baseline: 1.2021x; 1.2021x over previous
#include <cuda_runtime.h>
#include <math.h>
#include <stdint.h>

// ---------------------------------------------------------------------------
// Mamba2 block, B=2, T=1024, D_MODEL=2048, D_STATE=64, HEADDIM=64
// R8: all-fp32 pipeline (R2 structure) with packed f32x2 FFMA (FFMA2) in the
// GEMM inner product and the scan update — 2x fp32 FMA throughput on B300.
// No tensor-core paths (tcgen05 unreachable on base sm_103 target; mma.sync
// is FFMA-emulated — measured R4/R7).
// ---------------------------------------------------------------------------

#define B_     2
#define T_     1024
#define DM     2048
#define DIN    4096
#define DCONV  4224
#define DPROJ  8384
#define NH     64
#define NTOK   (B_ * T_)   // 2048

__device__ float g_u  [(size_t)NTOK * DM];
__device__ float g_zx [(size_t)NTOK * DPROJ];
__device__ float g_xbc[(size_t)NTOK * DCONV];
__device__ float g_dt [(size_t)NTOK * NH];
__device__ float g_dA [(size_t)NTOK * NH];
__device__ float g_y  [(size_t)NTOK * DIN];

__device__ __forceinline__ float sigmoidf_(float v) { return 1.f / (1.f + expf(-v)); }

// ---- packed f32x2 helpers (base Blackwell; SASS FFMA2) --------------------
#define FMAF2(d, a, b, c) \
    asm("fma.rn.f32x2 %0, %1, %2, %3;" : "=l"(d) : "l"(a), "l"(b), "l"(c))
#define MULF2(d, a, b) \
    asm("mul.rn.f32x2 %0, %1, %2;" : "=l"(d) : "l"(a), "l"(b))
__device__ __forceinline__ unsigned long long packdup(float x) {
    unsigned long long r;
    uint32_t xi = __float_as_uint(x);
    asm("mov.b64 %0, {%1,%1};" : "=l"(r) : "r"(xi));
    return r;
}
__device__ __forceinline__ float2 unpack2(unsigned long long v) {
    uint32_t lo, hi;
    asm("mov.b64 {%0,%1}, %2;" : "=r"(lo), "=r"(hi) : "l"(v));
    return make_float2(__uint_as_float(lo), __uint_as_float(hi));
}

// ---------------------------------------------------------------------------
// LayerNorm: one block per token row (D=2048)
// ---------------------------------------------------------------------------
__global__ void ln_kernel(const float* __restrict__ x,
                          const float* __restrict__ w,
                          const float* __restrict__ bb) {
    int r = blockIdx.x;
    const float* xr = x + (size_t)r * DM;
    float s = 0.f, s2 = 0.f;
    for (int i = threadIdx.x; i < DM; i += blockDim.x) {
        float v = xr[i]; s += v; s2 += v * v;
    }
    __shared__ float shs[32], shs2[32];
    int lane = threadIdx.x & 31, wid = threadIdx.x >> 5;
#pragma unroll
    for (int o = 16; o; o >>= 1) {
        s  += __shfl_xor_sync(0xffffffffu, s, o);
        s2 += __shfl_xor_sync(0xffffffffu, s2, o);
    }
    if (lane == 0) { shs[wid] = s; shs2[wid] = s2; }
    __syncthreads();
    __shared__ float mu_s, inv_s;
    if (threadIdx.x == 0) {
        float ts = 0.f, ts2 = 0.f;
        int nw = blockDim.x >> 5;
        for (int i = 0; i < nw; i++) { ts += shs[i]; ts2 += shs2[i]; }
        float mu = ts / DM;
        float var = ts2 / DM - mu * mu;
        mu_s = mu;
        inv_s = rsqrtf(var + 1e-5f);
    }
    __syncthreads();
    float mu = mu_s, inv = inv_s;
    for (int i = threadIdx.x; i < DM; i += blockDim.x)
        g_u[(size_t)r * DM + i] = (xr[i] - mu) * inv * w[i] + bb[i];
}

// ---------------------------------------------------------------------------
// SGEMM NT with FFMA2: C[m,n] = sum_k A[m,k] * Bw[n,k] (+Res[m,n])
// 128x128x8 tile, 256 threads, 8x8 microtile -> acc as 8x4 f32x2 pairs.
// Structure identical to the proven R2 kernel; only the MAC core is packed.
// ---------------------------------------------------------------------------
template<bool GUARD_N, bool RES>
__device__ __forceinline__ void sgemm_body(const float* __restrict__ A,
                                           const float* __restrict__ Bw,
                                           const float* __restrict__ Res,
                                           float* __restrict__ C,
                                           int M, int N, int K) {
    __shared__ __align__(16) float As[8][128];
    __shared__ __align__(16) float Bs[8][128];

    const int tid = threadIdx.x;
    const int m0 = blockIdx.y * 128;
    const int n0 = blockIdx.x * 128;

    const int lrow = tid >> 1;
    const int lcol = (tid & 1) << 2;

    const int tx = tid & 15;
    const int ty = tid >> 4;

    unsigned long long acc2[8][4];
#pragma unroll
    for (int i = 0; i < 8; i++)
#pragma unroll
        for (int j = 0; j < 4; j++) acc2[i][j] = 0ull;

    int brow = n0 + lrow;
    bool bval = true;
    if (GUARD_N && brow >= N) { brow = 0; bval = false; }

    const float* Ap = A  + (size_t)(m0 + lrow) * K + lcol;
    const float* Bp = Bw + (size_t)brow * K + lcol;

    for (int k0 = 0; k0 < K; k0 += 8) {
        float4 av = *reinterpret_cast<const float4*>(Ap + k0);
        float4 bv = *reinterpret_cast<const float4*>(Bp + k0);
        if (GUARD_N && !bval) bv = make_float4(0.f, 0.f, 0.f, 0.f);
        __syncthreads();
        As[lcol + 0][lrow] = av.x; As[lcol + 1][lrow] = av.y;
        As[lcol + 2][lrow] = av.z; As[lcol + 3][lrow] = av.w;
        Bs[lcol + 0][lrow] = bv.x; Bs[lcol + 1][lrow] = bv.y;
        Bs[lcol + 2][lrow] = bv.z; Bs[lcol + 3][lrow] = bv.w;
        __syncthreads();
#pragma unroll
        for (int kk = 0; kk < 8; kk++) {
            float a[8];
            float4 t;
            t = *reinterpret_cast<const float4*>(&As[kk][ty * 4]);
            a[0] = t.x; a[1] = t.y; a[2] = t.z; a[3] = t.w;
            t = *reinterpret_cast<const float4*>(&As[kk][ty * 4 + 64]);
            a[4] = t.x; a[5] = t.y; a[6] = t.z; a[7] = t.w;
            ulonglong2 bv0 = *reinterpret_cast<const ulonglong2*>(&Bs[kk][tx * 4]);
            ulonglong2 bv1 = *reinterpret_cast<const ulonglong2*>(&Bs[kk][tx * 4 + 64]);
            unsigned long long b0 = bv0.x, b1 = bv0.y, b2 = bv1.x, b3 = bv1.y;
#pragma unroll
            for (int i = 0; i < 8; i++) {
                unsigned long long a2 = packdup(a[i]);
                FMAF2(acc2[i][0], a2, b0, acc2[i][0]);
                FMAF2(acc2[i][1], a2, b1, acc2[i][1]);
                FMAF2(acc2[i][2], a2, b2, acc2[i][2]);
                FMAF2(acc2[i][3], a2, b3, acc2[i][3]);
            }
        }
    }

#pragma unroll
    for (int ih = 0; ih < 2; ih++) {
#pragma unroll
        for (int ii = 0; ii < 4; ii++) {
            int i = ih * 4 + ii;
            int m = m0 + ih * 64 + ty * 4 + ii;
#pragma unroll
            for (int jh = 0; jh < 2; jh++) {
                int n = n0 + jh * 64 + tx * 4;
                if (GUARD_N && n >= N) continue;   // N % 4 == 0, full float4 valid
                float2 p0 = unpack2(acc2[i][jh * 2 + 0]);
                float2 p1 = unpack2(acc2[i][jh * 2 + 1]);
                float4 v = make_float4(p0.x, p0.y, p1.x, p1.y);
                if (RES) {
                    float4 rv = *reinterpret_cast<const float4*>(Res + (size_t)m * N + n);
                    v.x += rv.x; v.y += rv.y; v.z += rv.z; v.w += rv.w;
                }
                *reinterpret_cast<float4*>(C + (size_t)m * N + n) = v;
            }
        }
    }
}

__global__ __launch_bounds__(256, 2)
void gemm1_kernel(const float* __restrict__ W) {
    sgemm_body<true, false>(g_u, W, nullptr, g_zx, NTOK, DPROJ, DM);
}

__global__ __launch_bounds__(256, 2)
void gemm2_kernel(const float* __restrict__ W,
                  const float* __restrict__ Res,
                  float* __restrict__ C) {
    sgemm_body<false, true>(g_y, W, Res, C, NTOK, DM, DIN);
}

// ---------------------------------------------------------------------------
// Depthwise causal conv (k=4) + SiLU. 32 t-chunks per batch.
// ---------------------------------------------------------------------------
#define CCH 32
__global__ void conv_kernel(const float* __restrict__ cw,
                            const float* __restrict__ cb) {
    int c = blockIdx.x * blockDim.x + threadIdx.x;
    if (c >= DCONV) return;
    int b = blockIdx.y >> 5;
    int chunk = blockIdx.y & 31;
    int t0 = chunk * CCH;
    float w0 = cw[c * 4 + 0], w1 = cw[c * 4 + 1];
    float w2 = cw[c * 4 + 2], w3 = cw[c * 4 + 3];
    float bias = cb[c];
    const float* src = g_zx + (size_t)b * T_ * DPROJ + DIN + c;
    float* dst = g_xbc + (size_t)b * T_ * DCONV + c;
    float x0 = (t0 >= 3) ? src[(size_t)(t0 - 3) * DPROJ] : 0.f;
    float x1 = (t0 >= 2) ? src[(size_t)(t0 - 2) * DPROJ] : 0.f;
    float x2 = (t0 >= 1) ? src[(size_t)(t0 - 1) * DPROJ] : 0.f;
    for (int t = t0; t < t0 + CCH; t++) {
        float x3 = src[(size_t)t * DPROJ];
        float v = bias + x0 * w0 + x1 * w1 + x2 * w2 + x3 * w3;
        v = v * sigmoidf_(v);
        dst[(size_t)t * DCONV] = v;
        x0 = x1; x1 = x2; x2 = x3;
    }
}

// ---------------------------------------------------------------------------
// dt = softplus(dt_raw + dt_bias), dA = exp(dt * -exp(A_log))
// dt_raw comes from the fp32 GEMM1 output (exact enough: rel_err 1.5e-6 in R2)
// ---------------------------------------------------------------------------
__global__ void dt_kernel(const float* __restrict__ dt_bias,
                          const float* __restrict__ A_log) {
    int r = blockIdx.x;
    int h = threadIdx.x;   // 64
    float raw = g_zx[(size_t)r * DPROJ + DIN + DCONV + h] + dt_bias[h];
    float dtv = (raw > 20.f) ? raw : log1pf(expf(raw));
    float Av = -expf(A_log[h]);
    g_dt[r * NH + h] = dtv;
    g_dA[r * NH + h] = expf(dtv * Av);
}

// ---------------------------------------------------------------------------
// Sequential selective scan with FFMA2. Block = (b, head), 64 threads.
// State h[p][0..63] as 32 f32x2 pairs in registers; B/C/x double-buffered in
// SMEM; per step: st2 = st2*dA2 + dtx2*B2 ; acc2 += st2*C2  (96 packed ops).
// ---------------------------------------------------------------------------
__global__ __launch_bounds__(64)
void scan_kernel(const float* __restrict__ Dvec) {
    int bh = blockIdx.x;
    int b = bh >> 6, hh = bh & 63;
    int p = threadIdx.x;

    __shared__ __align__(16) float sB[2][64];
    __shared__ __align__(16) float sC[2][64];
    __shared__ __align__(16) float sX[2][64];
    __shared__ float sS[2][2];   // [buf][0]=dA, [buf][1]=dt

    unsigned long long st2[32];
#pragma unroll
    for (int n = 0; n < 32; n++) st2[n] = 0ull;
    float Dh = Dvec[hh];

    const size_t base = (size_t)b * T_ * DCONV;
    {   // preload t = 0
        sX[0][p] = g_xbc[base + hh * 64 + p];
        sB[0][p] = g_xbc[base + 4096 + p];
        sC[0][p] = g_xbc[base + 4160 + p];
        if (p < 2) {
            int rr = b * T_;
            sS[0][p] = (p == 0) ? g_dA[rr * NH + hh] : g_dt[rr * NH + hh];
        }
    }

    for (int t = 0; t < T_; t++) {
        int buf = t & 1;
        __syncthreads();
        if (t + 1 < T_) {
            size_t rq = base + (size_t)(t + 1) * DCONV;
            sX[buf ^ 1][p] = g_xbc[rq + hh * 64 + p];
            sB[buf ^ 1][p] = g_xbc[rq + 4096 + p];
            sC[buf ^ 1][p] = g_xbc[rq + 4160 + p];
            if (p < 2) {
                int rr = b * T_ + t + 1;
                sS[buf ^ 1][p] = (p == 0) ? g_dA[rr * NH + hh] : g_dt[rr * NH + hh];
            }
        }
        float dAv = sS[buf][0];
        float dtx = sS[buf][1] * sX[buf][p];
        unsigned long long dA2  = packdup(dAv);
        unsigned long long dtx2 = packdup(dtx);
        unsigned long long acc2 = 0ull;
#pragma unroll
        for (int q = 0; q < 16; q++) {
            ulonglong2 b2 = *reinterpret_cast<const ulonglong2*>(&sB[buf][q * 4]);
            ulonglong2 c2 = *reinterpret_cast<const ulonglong2*>(&sC[buf][q * 4]);
            unsigned long long t0, t1;
            MULF2(t0, dtx2, b2.x);
            MULF2(t1, dtx2, b2.y);
            FMAF2(st2[q * 2 + 0], st2[q * 2 + 0], dA2, t0);
            FMAF2(st2[q * 2 + 1], st2[q * 2 + 1], dA2, t1);
            FMAF2(acc2, st2[q * 2 + 0], c2.x, acc2);
            FMAF2(acc2, st2[q * 2 + 1], c2.y, acc2);
        }
        float2 ac = unpack2(acc2);
        g_y[(size_t)(b * T_ + t) * DIN + hh * 64 + p] =
            (ac.x + ac.y) + Dh * sX[buf][p];
    }
}

// ---------------------------------------------------------------------------
// y = y * silu(z); y = y * rsqrt(mean(y^2)+eps) * norm_w. Block per token.
// ---------------------------------------------------------------------------
__global__ void gate_rms_kernel(const float* __restrict__ norm_w) {
    int r = blockIdx.x;
    float ss = 0.f;
    for (int i = threadIdx.x; i < DIN; i += blockDim.x) {
        float zv = g_zx[(size_t)r * DPROJ + i];
        float g = g_y[(size_t)r * DIN + i] * zv * sigmoidf_(zv);
        g_y[(size_t)r * DIN + i] = g;
        ss += g * g;
    }
    __shared__ float sh[32];
    int lane = threadIdx.x & 31, wid = threadIdx.x >> 5;
#pragma unroll
    for (int o = 16; o; o >>= 1) ss += __shfl_xor_sync(0xffffffffu, ss, o);
    if (lane == 0) sh[wid] = ss;
    __syncthreads();
    __shared__ float sc;
    if (threadIdx.x == 0) {
        float tot = 0.f;
        int nw = blockDim.x >> 5;
        for (int i = 0; i < nw; i++) tot += sh[i];
        sc = rsqrtf(tot / DIN + 1e-5f);
    }
    __syncthreads();
    float s = sc;
    for (int i = threadIdx.x; i < DIN; i += blockDim.x)
        g_y[(size_t)r * DIN + i] *= s * norm_w[i];
}

// ---------------------------------------------------------------------------
// launch
// ---------------------------------------------------------------------------
extern "C" void kernel_launch(void* const* d_in, const int* in_sizes, int n_in,
                              void* d_out, int out_size) {
    const float* x          = (const float*)d_in[0];
    const float* ln_w       = (const float*)d_in[1];
    const float* ln_b       = (const float*)d_in[2];
    const float* in_proj_w  = (const float*)d_in[3];
    const float* conv_w     = (const float*)d_in[4];
    const float* conv_b     = (const float*)d_in[5];
    const float* dt_bias    = (const float*)d_in[6];
    const float* A_log      = (const float*)d_in[7];
    const float* Dv         = (const float*)d_in[8];
    const float* norm_w     = (const float*)d_in[9];
    const float* out_proj_w = (const float*)d_in[10];
    float* out = (float*)d_out;

    ln_kernel<<<NTOK, 256>>>(x, ln_w, ln_b);
    gemm1_kernel<<<dim3((DPROJ + 127) / 128, NTOK / 128), 256>>>(in_proj_w);
    conv_kernel<<<dim3((DCONV + 255) / 256, B_ * 32), 256>>>(conv_w, conv_b);
    dt_kernel<<<NTOK, NH>>>(dt_bias, A_log);
    scan_kernel<<<B_ * NH, 64>>>(Dv);
    gate_rms_kernel<<<NTOK, 256>>>(norm_w);
    gemm2_kernel<<<dim3(DM / 128, NTOK / 128), 256>>>(out_proj_w, x, out);
}